// round 12
// baseline (speedup 1.0000x reference)
#include <cuda_runtime.h>
#include <cstdint>

#define N     8192
#define K1    31
#define CAP   256      // per-line candidate capacity (mean 88, max ~135)
#define PIVOT 2.3f     // P(z>2.3)=0.0107
#define NF4   ((size_t)N * N / 4)
#define FULLM 0xFFFFFFFFu

__device__ unsigned long long g_rowcand[(size_t)N * CAP]; // 16 MB
__device__ unsigned long long g_colcand[(size_t)N * CAP]; // 16 MB
__device__ int                g_rowcnt[N];
__device__ int                g_colcnt[N];
__device__ unsigned long long g_rowth[N];
__device__ unsigned long long g_colth[N];

// Monotone map float -> uint32 (larger float => larger key)
__device__ __forceinline__ unsigned int fkey(float x) {
    unsigned int u = __float_as_uint(x);
    return (u & 0x80000000u) ? ~u : (u | 0x80000000u);
}
__device__ __forceinline__ float inv_fkey(unsigned int k) {
    unsigned int u = (k & 0x80000000u) ? (k ^ 0x80000000u) : ~k;
    return __uint_as_float(u);
}
// Composite key: value-major, lower index wins ties (stable top_k semantics)
__device__ __forceinline__ unsigned long long ckey(float x, int idx) {
    return ((unsigned long long)fkey(x) << 32) | (unsigned int)(N - 1 - idx);
}

__global__ void zero_kernel() {
    int t = blockIdx.x * blockDim.x + threadIdx.x;
    if (t < N) { g_rowcnt[t] = 0; g_colcnt[t] = 0; }
}

// block-level exact fallback: K1-th largest key of a full line (exactness
// guard for arbitrary inputs; statistically never triggered)
template <bool ROW>
__device__ unsigned long long block_fallback(const float* __restrict__ A, int line) {
    __shared__ unsigned long long red[128];
    unsigned long long prev = 0xFFFFFFFFFFFFFFFFull;
    for (int it = 0; it < K1; it++) {
        unsigned long long best = 0;
        for (int t = threadIdx.x; t < N; t += 128) {
            float x = ROW ? A[(size_t)line * N + t] : A[(size_t)t * N + line];
            unsigned long long k = ckey(x, t);
            if (k < prev && k > best) best = k;
        }
        red[threadIdx.x] = best;
        __syncthreads();
        for (int s = 64; s > 0; s >>= 1) {
            if (threadIdx.x < s) {
                unsigned long long o = red[threadIdx.x + s];
                if (o > red[threadIdx.x]) red[threadIdx.x] = o;
            }
            __syncthreads();
        }
        prev = red[0];
        __syncthreads();
    }
    return prev;
}

// K1: coalesced flat stream. Reads A, writes zeros, and builds BOTH candidate
// lists: row pushes are warp-aggregated (1 atomic/warp), column pushes are
// per-candidate (~1.4/warp, independent).
__global__ __launch_bounds__(256) void stream_kernel(const float* __restrict__ A,
                                                     float* __restrict__ out) {
    const size_t g = (size_t)blockIdx.x * 256 + threadIdx.x;  // float4 index
    float4 v = __ldcs(&((const float4*)A)[g]);
    const float4 zz = {0.0f, 0.0f, 0.0f, 0.0f};
    __stcs(&((float4*)out)[g], zz);

    unsigned m0 = __ballot_sync(FULLM, v.x > PIVOT);
    unsigned m1 = __ballot_sync(FULLM, v.y > PIVOT);
    unsigned m2 = __ballot_sync(FULLM, v.z > PIVOT);
    unsigned m3 = __ballot_sync(FULLM, v.w > PIVOT);
    const int nc = __popc(m0) + __popc(m1) + __popc(m2) + __popc(m3);
    if (nc == 0) return;

    const int lane = threadIdx.x & 31;
    const unsigned lt = (1u << lane) - 1u;
    const int i = (int)(g >> 11);              // row (2048 float4 per row)
    const int j0 = (int)(g & 2047) * 4;        // element index of v.x

    int base = 0;
    if (lane == 0) base = atomicAdd(&g_rowcnt[i], nc);
    base = __shfl_sync(FULLM, base, 0);

    const int p1 = __popc(m0), p2 = p1 + __popc(m1), p3 = p2 + __popc(m2);
    float xs[4] = {v.x, v.y, v.z, v.w};
    const int pre[4] = {0, p1, p2, p3};
    const unsigned ms[4] = {m0, m1, m2, m3};
#pragma unroll
    for (int c = 0; c < 4; c++) {
        float x = xs[c];
        if (x > PIVOT) {
            const int j = j0 + c;
            const int slot = base + pre[c] + __popc(ms[c] & lt);
            if (slot < CAP) g_rowcand[(size_t)i * CAP + slot] = ckey(x, j);
            int cs = atomicAdd(&g_colcnt[j], 1);
            if (cs < CAP) g_colcand[(size_t)j * CAP + cs] = ckey(x, i);
        }
    }
}

// K2: merged thresholds. Block b<N -> row b; b>=N -> column b-N.
// Rank-count the candidate list; exact fallback on under/overflow
// (rows additionally flagged unhealthy via g_rowcnt = -1 for K3).
__global__ __launch_bounds__(128) void thresh_kernel(const float* __restrict__ A) {
    const bool isrow = (blockIdx.x < N);
    const int line = isrow ? blockIdx.x : blockIdx.x - N;
    const int t = threadIdx.x;
    const int c = isrow ? g_rowcnt[line] : g_colcnt[line];
    const unsigned long long* list = isrow ? &g_rowcand[(size_t)line * CAP]
                                           : &g_colcand[(size_t)line * CAP];
    __shared__ unsigned long long cand[CAP];

    if (c >= K1 && c <= CAP) {
        for (int s = t; s < c; s += 128) cand[s] = list[s];
        __syncthreads();
        for (int s = t; s < c; s += 128) {
            unsigned long long kt = cand[s];
            int r = 0;
            for (int m = 0; m < c; m++) r += (cand[m] > kt);
            if (r == K1 - 1) {
                if (isrow) g_rowth[line] = kt; else g_colth[line] = kt;
            }
        }
    } else {
        unsigned long long th = isrow ? block_fallback<true>(A, line)
                                      : block_fallback<false>(A, line);
        if (t == 0) {
            if (isrow) { g_rowth[line] = th; g_rowcnt[line] = -1; }
            else       g_colth[line] = th;
        }
    }
}

// K3: scatter survivors from ROW lists (row-major writes). Unhealthy rows
// (g_rowcnt = -1) rescan the full row — exact for any input.
__global__ __launch_bounds__(128) void scatter_kernel(const float* __restrict__ A,
                                                      float* __restrict__ out) {
    const int row = blockIdx.x, t = threadIdx.x;
    const int cnt = g_rowcnt[row];
    const unsigned long long rth = g_rowth[row];
    if (cnt >= 0) {
        for (int s = t; s < cnt; s += 128) {
            unsigned long long k = g_rowcand[(size_t)row * CAP + s];
            if (k < rth) continue;
            int j = N - 1 - (int)(unsigned int)(k & 0xFFFFFFFFu);
            if (j == row) continue;
            float x = inv_fkey((unsigned int)(k >> 32));
            if (ckey(x, row) >= g_colth[j])
                out[(size_t)row * N + j] = x;
        }
    } else {
        for (int j = t; j < N; j += 128) {
            if (j == row) continue;
            float x = A[(size_t)row * N + j];
            if (ckey(x, j) >= rth && ckey(x, row) >= g_colth[j])
                out[(size_t)row * N + j] = x;
        }
    }
}

extern "C" void kernel_launch(void* const* d_in, const int* in_sizes, int n_in,
                              void* d_out, int out_size) {
    const float* A = (const float*)d_in[0];
    float* out = (float*)d_out;
    zero_kernel<<<(N + 255) / 256, 256>>>();
    stream_kernel<<<(unsigned)(NF4 / 256), 256>>>(A, out);
    thresh_kernel<<<2 * N, 128>>>(A);
    scatter_kernel<<<N, 128>>>(A, out);
}

// round 13
// speedup vs baseline: 1.2703x; 1.2703x over previous
#include <cuda_runtime.h>
#include <cstdint>

#define N     8192
#define K1    31
#define CAP   256      // per-line candidate capacity (mean 88, max ~135)
#define PIVOT 2.3f     // P(z>2.3)=0.0107 -> E[cand]=88 per line
#define FULLM 0xFFFFFFFFu

__device__ unsigned long long g_colcand[(size_t)N * CAP]; // 16 MB
__device__ int                g_colcnt[N];
__device__ unsigned long long g_rowth[N];

// Monotone map float -> uint32 (larger float => larger key)
__device__ __forceinline__ unsigned int fkey(float x) {
    unsigned int u = __float_as_uint(x);
    return (u & 0x80000000u) ? ~u : (u | 0x80000000u);
}
__device__ __forceinline__ float inv_fkey(unsigned int k) {
    unsigned int u = (k & 0x80000000u) ? (k ^ 0x80000000u) : ~k;
    return __uint_as_float(u);
}
// Composite key: value-major, lower index wins ties (stable top_k semantics)
__device__ __forceinline__ unsigned long long ckey(float x, int idx) {
    return ((unsigned long long)fkey(x) << 32) | (unsigned int)(N - 1 - idx);
}

__global__ void zero_kernel() {
    int t = blockIdx.x * blockDim.x + threadIdx.x;
    if (t < N) g_colcnt[t] = 0;
}

// block-level exact fallback: K1-th largest key of a full line (exactness
// guard for arbitrary inputs; statistically never triggered)
template <bool ROW, int BT>
__device__ unsigned long long block_fallback(const float* __restrict__ A, int line) {
    __shared__ unsigned long long red[BT];
    unsigned long long prev = 0xFFFFFFFFFFFFFFFFull;
    for (int it = 0; it < K1; it++) {
        unsigned long long best = 0;
        for (int t = threadIdx.x; t < N; t += BT) {
            float x = ROW ? A[(size_t)line * N + t] : A[(size_t)t * N + line];
            unsigned long long k = ckey(x, t);
            if (k < prev && k > best) best = k;
        }
        red[threadIdx.x] = best;
        __syncthreads();
        for (int s = BT / 2; s > 0; s >>= 1) {
            if (threadIdx.x < s) {
                unsigned long long o = red[threadIdx.x + s];
                if (o > red[threadIdx.x]) red[threadIdx.x] = o;
            }
            __syncthreads();
        }
        prev = red[0];
        __syncthreads();
    }
    return prev;
}

// K1: row per block. ALL 8 loads front-batched (MLP=8) + zero-stores issued
// before any push work. Row candidates: ballot-compacted into smem (one smem
// atomic per nonempty 128-element group). Column candidates: independent
// ATOMG pushes overlapping the streaming. rowth rank-counted in-block.
__global__ __launch_bounds__(256) void rows_kernel(const float* __restrict__ A,
                                                   float* __restrict__ out) {
    const int i = blockIdx.x, t = threadIdx.x, lane = t & 31;
    const float4* Ap = (const float4*)(A + (size_t)i * N);
    float4* Op = (float4*)(out + (size_t)i * N);

    float4 v[8];
#pragma unroll
    for (int q = 0; q < 8; q++) v[q] = __ldcs(&Ap[q * 256 + t]);
    const float4 zz = {0.0f, 0.0f, 0.0f, 0.0f};
#pragma unroll
    for (int q = 0; q < 8; q++) __stcs(&Op[q * 256 + t], zz);

    __shared__ unsigned long long cand[CAP];
    __shared__ int cnt;
    if (t == 0) cnt = 0;
    __syncthreads();

    const unsigned lt = (1u << lane) - 1u;
#pragma unroll
    for (int q = 0; q < 8; q++) {
        float xs[4] = {v[q].x, v[q].y, v[q].z, v[q].w};
#pragma unroll
        for (int c = 0; c < 4; c++) {
            const bool p = xs[c] > PIVOT;
            const unsigned m = __ballot_sync(FULLM, p);
            if (m) {
                const int leader = __ffs(m) - 1;
                int base = 0;
                if (lane == leader) base = atomicAdd(&cnt, __popc(m));
                base = __shfl_sync(FULLM, base, leader);
                if (p) {
                    const int j = (q * 256 + t) * 4 + c;
                    const int slot = base + __popc(m & lt);
                    if (slot < CAP) cand[slot] = ckey(xs[c], j);
                    int cs = atomicAdd(&g_colcnt[j], 1);
                    if (cs < CAP) g_colcand[(size_t)j * CAP + cs] = ckey(xs[c], i);
                }
            }
        }
    }
    __syncthreads();

    const int total = cnt;
    if (total >= K1 && total <= CAP) {
        for (int s = t; s < total; s += 256) {
            unsigned long long kt = cand[s];
            int r = 0;
            for (int m = 0; m < total; m++) r += (cand[m] > kt);
            if (r == K1 - 1) g_rowth[i] = kt;   // exactly one writer
        }
    } else {
        unsigned long long th = block_fallback<true, 256>(A, i);
        if (t == 0) g_rowth[i] = th;
    }
}

// K2: block per column (128 thr). colth by rank-counting the candidate list,
// then scatter survivors in-place. Every entry passing BOTH thresholds in a
// healthy column has value > PIVOT, hence is in the list. Unhealthy columns
// (under/overflow): exact threshold + full-column rescan.
__global__ __launch_bounds__(128) void colth_scatter_kernel(const float* __restrict__ A,
                                                            float* __restrict__ out) {
    const int j = blockIdx.x, t = threadIdx.x;
    const int c = g_colcnt[j];
    __shared__ unsigned long long cand[CAP];
    __shared__ unsigned long long s_cth;

    if (c >= K1 && c <= CAP) {
        for (int s = t; s < c; s += 128)
            cand[s] = g_colcand[(size_t)j * CAP + s];
        __syncthreads();
        for (int s = t; s < c; s += 128) {
            unsigned long long kt = cand[s];
            int r = 0;
            for (int m = 0; m < c; m++) r += (cand[m] > kt);
            if (r == K1 - 1) s_cth = kt;
        }
        __syncthreads();
        const unsigned long long cth = s_cth;
        for (int s = t; s < c; s += 128) {
            unsigned long long k = cand[s];
            if (k < cth) continue;
            int i = N - 1 - (int)(unsigned int)(k & 0xFFFFFFFFu);
            if (i == j) continue;
            float x = inv_fkey((unsigned int)(k >> 32));
            if (ckey(x, j) >= g_rowth[i])
                out[(size_t)i * N + j] = x;
        }
    } else {
        unsigned long long cth = block_fallback<false, 128>(A, j);
        for (int i = t; i < N; i += 128) {
            if (i == j) continue;
            float x = A[(size_t)i * N + j];
            if (ckey(x, i) >= cth && ckey(x, j) >= g_rowth[i])
                out[(size_t)i * N + j] = x;
        }
    }
}

extern "C" void kernel_launch(void* const* d_in, const int* in_sizes, int n_in,
                              void* d_out, int out_size) {
    const float* A = (const float*)d_in[0];
    float* out = (float*)d_out;
    zero_kernel<<<(N + 255) / 256, 256>>>();
    rows_kernel<<<N, 256>>>(A, out);
    colth_scatter_kernel<<<N, 128>>>(A, out);
}

// round 14
// speedup vs baseline: 1.2729x; 1.0020x over previous
#include <cuda_runtime.h>
#include <cstdint>

#define N     8192
#define K1    31
#define CAP   256      // per-line candidate capacity (mean 88, max ~135)
#define PIVOT 2.3f     // P(z>2.3)=0.0107 -> E[cand]=88 per line
#define NF4   ((size_t)N * N / 4)
#define NREC  ((size_t)N * N / 128)   // one record per warp (128 elements)
#define FULLM 0xFFFFFFFFu

__device__ uint4              g_bits[NREC];               // 8 MB bitmask
__device__ float              g_slots[NREC * 4];          // 32 MB first-4 values/record
__device__ unsigned long long g_colcand[(size_t)N * CAP]; // 16 MB
__device__ int                g_colcnt[N];
__device__ unsigned long long g_rowth[N];

// Monotone map float -> uint32 (larger float => larger key)
__device__ __forceinline__ unsigned int fkey(float x) {
    unsigned int u = __float_as_uint(x);
    return (u & 0x80000000u) ? ~u : (u | 0x80000000u);
}
__device__ __forceinline__ float inv_fkey(unsigned int k) {
    unsigned int u = (k & 0x80000000u) ? (k ^ 0x80000000u) : ~k;
    return __uint_as_float(u);
}
// Composite key: value-major, lower index wins ties (stable top_k semantics)
__device__ __forceinline__ unsigned long long ckey(float x, int idx) {
    return ((unsigned long long)fkey(x) << 32) | (unsigned int)(N - 1 - idx);
}

// block-level exact fallback: K1-th largest key of a full line (exactness
// guard for arbitrary inputs; statistically never triggered)
template <bool ROW, int BT>
__device__ unsigned long long block_fallback(const float* __restrict__ A, int line) {
    __shared__ unsigned long long red[BT];
    unsigned long long prev = 0xFFFFFFFFFFFFFFFFull;
    for (int it = 0; it < K1; it++) {
        unsigned long long best = 0;
        for (int t = threadIdx.x; t < N; t += BT) {
            float x = ROW ? A[(size_t)line * N + t] : A[(size_t)t * N + line];
            unsigned long long k = ckey(x, t);
            if (k < prev && k > best) best = k;
        }
        red[threadIdx.x] = best;
        __syncthreads();
        for (int s = BT / 2; s > 0; s >>= 1) {
            if (threadIdx.x < s) {
                unsigned long long o = red[threadIdx.x + s];
                if (o > red[threadIdx.x]) red[threadIdx.x] = o;
            }
            __syncthreads();
        }
        prev = red[0];
        __syncthreads();
    }
    return prev;
}

// K1: pure stream (measured ~86us). Reads A (.cs), zeros out (.cs), writes
// bitmask + first-4 values per record (cacheable -> L2-resident for K2).
// Record gw: element gw*128 + lane*4 + c; ordinal = word-major (c), then lane.
__global__ __launch_bounds__(256) void stream_kernel(const float* __restrict__ A,
                                                     float* __restrict__ out) {
    if (blockIdx.x < N / 256) g_colcnt[blockIdx.x * 256 + threadIdx.x] = 0;
    const size_t g = (size_t)blockIdx.x * 256 + threadIdx.x;  // float4 index
    float4 v = __ldcs(&((const float4*)A)[g]);
    const float4 zz = {0.0f, 0.0f, 0.0f, 0.0f};
    __stcs(&((float4*)out)[g], zz);
    unsigned m0 = __ballot_sync(FULLM, v.x > PIVOT);
    unsigned m1 = __ballot_sync(FULLM, v.y > PIVOT);
    unsigned m2 = __ballot_sync(FULLM, v.z > PIVOT);
    unsigned m3 = __ballot_sync(FULLM, v.w > PIVOT);
    const int lane = threadIdx.x & 31;
    const unsigned lt = (1u << lane) - 1u;
    const size_t gw = g >> 5;
    const int p1 = __popc(m0), p2 = p1 + __popc(m1), p3 = p2 + __popc(m2);
    if (v.x > PIVOT) { int o = __popc(m0 & lt);      if (o < 4) g_slots[gw * 4 + o] = v.x; }
    if (v.y > PIVOT) { int o = p1 + __popc(m1 & lt); if (o < 4) g_slots[gw * 4 + o] = v.y; }
    if (v.z > PIVOT) { int o = p2 + __popc(m2 & lt); if (o < 4) g_slots[gw * 4 + o] = v.z; }
    if (v.w > PIVOT) { int o = p3 + __popc(m3 & lt); if (o < 4) g_slots[gw * 4 + o] = v.w; }
    if (lane == 0) {
        uint4 w = {m0, m1, m2, m3};
        g_bits[gw] = w;
    }
}

// K2: block per row. Coalesced bits+slots load (L2), compact keys to smem,
// rank-count rowth, then push column candidates: ONE independent atomic per
// thread (no dependent chains). Column key spliced from row key bits.
__global__ __launch_bounds__(256) void rowth_push_kernel(const float* __restrict__ A) {
    const int i = blockIdx.x, t = threadIdx.x, lane = t & 31, w = t >> 5;
    __shared__ unsigned long long keys[CAP];
    __shared__ int wsum[2];

    uint4 b = {0, 0, 0, 0};
    float4 sv = {0, 0, 0, 0};
    int cnt = 0;
    if (t < 64) {
        b = g_bits[(size_t)i * 64 + t];
        sv = ((const float4*)g_slots)[(size_t)i * 64 + t];
        cnt = __popc(b.x) + __popc(b.y) + __popc(b.z) + __popc(b.w);
    }
    int incl = cnt;
#pragma unroll
    for (int d = 1; d < 32; d <<= 1) {
        int vv = __shfl_up_sync(FULLM, incl, d);
        if (lane >= d) incl += vv;
    }
    if (w < 2 && lane == 31) wsum[w] = incl;
    __syncthreads();
    const int total = wsum[0] + wsum[1];
    const bool fits = (total <= CAP);
    int base = incl - cnt + ((w == 1) ? wsum[0] : 0);

    if (t < 64 && cnt) {
        unsigned words[4] = {b.x, b.y, b.z, b.w};
        float slotv[4] = {sv.x, sv.y, sv.z, sv.w};
        int o = 0;
#pragma unroll
        for (int c = 0; c < 4; c++) {
            unsigned wb = words[c];
            while (wb) {
                int l = __ffs(wb) - 1;
                wb &= wb - 1;
                int j = t * 128 + l * 4 + c;
                float x = (o < 4) ? slotv[o] : A[(size_t)i * N + j];  // rare overflow
                if (fits) keys[base + o] = ckey(x, j);
                else {  // ultra-rare: push inline, list skipped
                    int cs = atomicAdd(&g_colcnt[j], 1);
                    if (cs < CAP) g_colcand[(size_t)j * CAP + cs] = ckey(x, i);
                }
                o++;
            }
        }
    }
    __syncthreads();

    if (fits && total >= K1) {
        // rank-count rowth: each thread owns <=1 key
        if (t < total) {
            unsigned long long kt = keys[t];
            int r = 0;
            for (int m = 0; m < total; m++) r += (keys[m] > kt);
            if (r == K1 - 1) g_rowth[i] = kt;   // exactly one writer
        }
        // push phase: one independent atomic+store per thread
        if (t < total) {
            unsigned long long k = keys[t];
            int j = N - 1 - (int)(unsigned int)(k & 0xFFFFFFFFu);
            unsigned long long colk = (k & 0xFFFFFFFF00000000ull) | (unsigned int)(N - 1 - i);
            int cs = atomicAdd(&g_colcnt[j], 1);
            if (cs < CAP) g_colcand[(size_t)j * CAP + cs] = colk;
        }
    } else {
        if (fits) {  // underflow: push what exists, exact fallback for rowth
            if (t < total) {
                unsigned long long k = keys[t];
                int j = N - 1 - (int)(unsigned int)(k & 0xFFFFFFFFu);
                unsigned long long colk = (k & 0xFFFFFFFF00000000ull) | (unsigned int)(N - 1 - i);
                int cs = atomicAdd(&g_colcnt[j], 1);
                if (cs < CAP) g_colcand[(size_t)j * CAP + cs] = colk;
            }
            __syncthreads();
        }
        unsigned long long th = block_fallback<true, 256>(A, i);
        if (t == 0) g_rowth[i] = th;
    }
}

// K3: block per column (128 thr). colth by rank-counting the list, then
// scatter survivors. Healthy columns: every survivor is > PIVOT and in the
// list. Unhealthy (under/overflow): exact threshold + full-column rescan.
__global__ __launch_bounds__(128) void colth_scatter_kernel(const float* __restrict__ A,
                                                            float* __restrict__ out) {
    const int j = blockIdx.x, t = threadIdx.x;
    const int c = g_colcnt[j];
    __shared__ unsigned long long cand[CAP];
    __shared__ unsigned long long s_cth;

    if (c >= K1 && c <= CAP) {
        for (int s = t; s < c; s += 128)
            cand[s] = g_colcand[(size_t)j * CAP + s];
        __syncthreads();
        for (int s = t; s < c; s += 128) {
            unsigned long long kt = cand[s];
            int r = 0;
            for (int m = 0; m < c; m++) r += (cand[m] > kt);
            if (r == K1 - 1) s_cth = kt;
        }
        __syncthreads();
        const unsigned long long cth = s_cth;
        for (int s = t; s < c; s += 128) {
            unsigned long long k = cand[s];
            if (k < cth) continue;
            int i = N - 1 - (int)(unsigned int)(k & 0xFFFFFFFFu);
            if (i == j) continue;
            float x = inv_fkey((unsigned int)(k >> 32));
            if (ckey(x, j) >= g_rowth[i])
                out[(size_t)i * N + j] = x;
        }
    } else {
        unsigned long long cth = block_fallback<false, 128>(A, j);
        for (int i = t; i < N; i += 128) {
            if (i == j) continue;
            float x = A[(size_t)i * N + j];
            if (ckey(x, i) >= cth && ckey(x, j) >= g_rowth[i])
                out[(size_t)i * N + j] = x;
        }
    }
}

extern "C" void kernel_launch(void* const* d_in, const int* in_sizes, int n_in,
                              void* d_out, int out_size) {
    const float* A = (const float*)d_in[0];
    float* out = (float*)d_out;
    stream_kernel<<<(unsigned)(NF4 / 256), 256>>>(A, out);
    rowth_push_kernel<<<N, 256>>>(A);
    colth_scatter_kernel<<<N, 128>>>(A, out);
}

// round 15
// speedup vs baseline: 1.3688x; 1.0754x over previous
#include <cuda_runtime.h>
#include <cstdint>

#define N     8192
#define K1    31
#define CAP   256      // per-line candidate capacity (mean 88, max ~135)
#define PIVOT 2.3f     // P(z>2.3)=0.0107 -> E[cand]=88 per line
#define NF4   ((size_t)N * N / 4)
#define FULLM 0xFFFFFFFFu

__device__ uint4              g_bits[(size_t)N * N / 128]; // 8 MB bitmask (1 rec / 128 elems)
__device__ unsigned long long g_colcand[(size_t)N * CAP];  // 16 MB
__device__ int                g_colcnt[N];
__device__ unsigned long long g_rowth[N];

// Monotone map float -> uint32 (larger float => larger key)
__device__ __forceinline__ unsigned int fkey(float x) {
    unsigned int u = __float_as_uint(x);
    return (u & 0x80000000u) ? ~u : (u | 0x80000000u);
}
__device__ __forceinline__ float inv_fkey(unsigned int k) {
    unsigned int u = (k & 0x80000000u) ? (k ^ 0x80000000u) : ~k;
    return __uint_as_float(u);
}
// Composite key: value-major, lower index wins ties (stable top_k semantics)
__device__ __forceinline__ unsigned long long ckey(float x, int idx) {
    return ((unsigned long long)fkey(x) << 32) | (unsigned int)(N - 1 - idx);
}

// block-level exact fallback: K1-th largest key of a full line (exactness
// guard for arbitrary inputs; statistically never triggered)
template <bool ROW, int BT>
__device__ unsigned long long block_fallback(const float* __restrict__ A, int line) {
    __shared__ unsigned long long red[BT];
    unsigned long long prev = 0xFFFFFFFFFFFFFFFFull;
    for (int it = 0; it < K1; it++) {
        unsigned long long best = 0;
        for (int t = threadIdx.x; t < N; t += BT) {
            float x = ROW ? A[(size_t)line * N + t] : A[(size_t)t * N + line];
            unsigned long long k = ckey(x, t);
            if (k < prev && k > best) best = k;
        }
        red[threadIdx.x] = best;
        __syncthreads();
        for (int s = BT / 2; s > 0; s >>= 1) {
            if (threadIdx.x < s) {
                unsigned long long o = red[threadIdx.x + s];
                if (o > red[threadIdx.x]) red[threadIdx.x] = o;
            }
            __syncthreads();
        }
        prev = red[0];
        __syncthreads();
    }
    return prev;
}

// K1: PURE streaming pass (measured 78.9us @ 6.3TB/s). Reads A (.cs), zeros
// out (.cs), emits bitmask via ballots; first 32 blocks zero g_colcnt.
// Record gw covers elements gw*128 + lane*4 + c (word c, bit lane).
__global__ __launch_bounds__(256) void stream_kernel(const float* __restrict__ A,
                                                     float* __restrict__ out) {
    if (blockIdx.x < N / 256) g_colcnt[blockIdx.x * 256 + threadIdx.x] = 0;
    const size_t g = (size_t)blockIdx.x * 256 + threadIdx.x;  // float4 index
    float4 v = __ldcs(&((const float4*)A)[g]);
    const float4 zz = {0.0f, 0.0f, 0.0f, 0.0f};
    __stcs(&((float4*)out)[g], zz);
    unsigned m0 = __ballot_sync(FULLM, v.x > PIVOT);
    unsigned m1 = __ballot_sync(FULLM, v.y > PIVOT);
    unsigned m2 = __ballot_sync(FULLM, v.z > PIVOT);
    unsigned m3 = __ballot_sync(FULLM, v.w > PIVOT);
    if ((threadIdx.x & 31) == 0) {
        uint4 w = {m0, m1, m2, m3};
        g_bits[g >> 5] = w;
    }
}

// K2: block per row. Phase A: decode bit positions into smem (ALU only).
// Phase B: ONE independent gather + ONE independent column push per thread.
// Phase C: rank-count rowth. No dependent memory chains anywhere.
__global__ __launch_bounds__(256) void rowth_push_kernel(const float* __restrict__ A) {
    const int i = blockIdx.x, t = threadIdx.x, lane = t & 31, w = t >> 5;
    __shared__ unsigned short idxs[CAP];
    __shared__ unsigned long long keys[CAP];
    __shared__ int wsum[2];

    uint4 b = {0, 0, 0, 0};
    int cnt = 0;
    if (t < 64) {
        b = g_bits[(size_t)i * 64 + t];
        cnt = __popc(b.x) + __popc(b.y) + __popc(b.z) + __popc(b.w);
    }
    int incl = cnt;
#pragma unroll
    for (int d = 1; d < 32; d <<= 1) {
        int vv = __shfl_up_sync(FULLM, incl, d);
        if (lane >= d) incl += vv;
    }
    if (w < 2 && lane == 31) wsum[w] = incl;
    __syncthreads();
    const int total = wsum[0] + wsum[1];
    const bool fits = (total <= CAP);
    int off = incl - cnt + ((w == 1) ? wsum[0] : 0);

    if (t < 64 && cnt) {
        unsigned words[4] = {b.x, b.y, b.z, b.w};
#pragma unroll
        for (int c = 0; c < 4; c++) {
            unsigned wb = words[c];
            while (wb) {
                int l = __ffs(wb) - 1;
                wb &= wb - 1;
                int j = t * 128 + l * 4 + c;
                if (fits) idxs[off] = (unsigned short)j;
                else {  // ultra-rare overflow: inline gather+push, list skipped
                    float x = A[(size_t)i * N + j];
                    int cs = atomicAdd(&g_colcnt[j], 1);
                    if (cs < CAP) g_colcand[(size_t)j * CAP + cs] = ckey(x, i);
                }
                off++;
            }
        }
    }
    __syncthreads();

    if (fits && t < total) {
        const int j = idxs[t];
        const float x = A[(size_t)i * N + j];      // 1 independent load/thread
        const unsigned long long k = ckey(x, j);
        keys[t] = k;
        const unsigned long long colk =
            (k & 0xFFFFFFFF00000000ull) | (unsigned int)(N - 1 - i);
        int cs = atomicAdd(&g_colcnt[j], 1);        // 1 independent atomic/thread
        if (cs < CAP) g_colcand[(size_t)j * CAP + cs] = colk;
    }
    __syncthreads();

    if (fits && total >= K1) {
        if (t < total) {
            unsigned long long kt = keys[t];
            int r = 0;
            for (int m = 0; m < total; m++) r += (keys[m] > kt);
            if (r == K1 - 1) g_rowth[i] = kt;       // exactly one writer
        }
    } else {
        unsigned long long th = block_fallback<true, 256>(A, i);
        if (t == 0) g_rowth[i] = th;
    }
}

// K3: block per column (128 thr). colth by rank-counting the list, then
// scatter survivors. Healthy columns: every survivor is > PIVOT and in the
// list. Unhealthy (under/overflow): exact threshold + full-column rescan.
__global__ __launch_bounds__(128) void colth_scatter_kernel(const float* __restrict__ A,
                                                            float* __restrict__ out) {
    const int j = blockIdx.x, t = threadIdx.x;
    const int c = g_colcnt[j];
    __shared__ unsigned long long cand[CAP];
    __shared__ unsigned long long s_cth;

    if (c >= K1 && c <= CAP) {
        for (int s = t; s < c; s += 128)
            cand[s] = g_colcand[(size_t)j * CAP + s];
        __syncthreads();
        for (int s = t; s < c; s += 128) {
            unsigned long long kt = cand[s];
            int r = 0;
            for (int m = 0; m < c; m++) r += (cand[m] > kt);
            if (r == K1 - 1) s_cth = kt;
        }
        __syncthreads();
        const unsigned long long cth = s_cth;
        for (int s = t; s < c; s += 128) {
            unsigned long long k = cand[s];
            if (k < cth) continue;
            int i = N - 1 - (int)(unsigned int)(k & 0xFFFFFFFFu);
            if (i == j) continue;
            float x = inv_fkey((unsigned int)(k >> 32));
            if (ckey(x, j) >= g_rowth[i])
                out[(size_t)i * N + j] = x;
        }
    } else {
        unsigned long long cth = block_fallback<false, 128>(A, j);
        for (int i = t; i < N; i += 128) {
            if (i == j) continue;
            float x = A[(size_t)i * N + j];
            if (ckey(x, i) >= cth && ckey(x, j) >= g_rowth[i])
                out[(size_t)i * N + j] = x;
        }
    }
}

extern "C" void kernel_launch(void* const* d_in, const int* in_sizes, int n_in,
                              void* d_out, int out_size) {
    const float* A = (const float*)d_in[0];
    float* out = (float*)d_out;
    stream_kernel<<<(unsigned)(NF4 / 256), 256>>>(A, out);
    rowth_push_kernel<<<N, 256>>>(A);
    colth_scatter_kernel<<<N, 128>>>(A, out);
}